// round 10
// baseline (speedup 1.0000x reference)
#include <cuda_runtime.h>
#include <cuda_bf16.h>
#include <math.h>

#define OUT_G 12
#define V_G (OUT_G * OUT_G * OUT_G)   // 1728
#define MAXN 256
#define NB 16                          // spatial bins per dim
#define NBINS (NB * NB * NB)           // 4096
#define NWMAX 4                        // mask words (up to 256 rois)
#define DOM_LO (-12.0f)
#define DOM_HI (12.0f)
#define CELL ((DOM_HI - DOM_LO) / (float)NB)   // 1.5
#define FIN_BLOCKS 128
#define FIN_THREADS 256

// Scratch (__device__ globals: allocation-free rule; BSS zero-init = base case)
__device__ float g_roi[MAXN * 12];     // cx,cy,czc,cosa,sina,hx,hy,hz,vx,vy,vz,rad2
__device__ float g_aabb[MAXN * 6];     // xlo,xhi,ylo,yhi,zlo,zhi
__device__ int g_count[MAXN * V_G];
__device__ unsigned long long g_mask[NBINS * NWMAX];
__device__ int g_touched[MAXN * V_G];  // compacted list of occupied (roi,voxel) ids
__device__ int g_ntouched;             // reset by finalize last block each run
__device__ int g_done;                 // finalize arrival counter

__device__ __forceinline__ unsigned enc_f(float f) {
    unsigned u = __float_as_uint(f);
    return (u & 0x80000000u) ? ~u : (u | 0x80000000u);
}
__device__ __forceinline__ float dec_f(unsigned u) {
    return (u & 0x80000000u) ? __uint_as_float(u & 0x7FFFFFFFu) : __uint_as_float(~u);
}

// ---------------------------------------------------------------------------
// Kernel 1: per-roi params + AABB. Tiny (N threads).
// ---------------------------------------------------------------------------
__global__ void roi_params_kernel(const float* __restrict__ rois, int N) {
    int r = blockIdx.x * blockDim.x + threadIdx.x;
    if (r >= N) return;
    float cx = rois[7 * r + 0];
    float cy = rois[7 * r + 1];
    float czb = rois[7 * r + 2];
    float dx = rois[7 * r + 3];
    float dy = rois[7 * r + 4];
    float dz = rois[7 * r + 5];
    float rz = rois[7 * r + 6];
    float czc = czb + dz * 0.5f;
    float cosa = cosf(-rz);
    float sina = sinf(-rz);
    float hx = dx * 0.5f, hy = dy * 0.5f, hz = dz * 0.5f;
    float* R = &g_roi[r * 12];
    R[0] = cx; R[1] = cy; R[2] = czc; R[3] = cosa; R[4] = sina;
    R[5] = hx; R[6] = hy; R[7] = hz;
    R[8] = dx / (float)OUT_G; R[9] = dy / (float)OUT_G; R[10] = dz / (float)OUT_G;
    R[11] = hx * hx + hy * hy;
    float ex = fabsf(hx * cosa) + fabsf(hy * sina);
    float ey = fabsf(hx * sina) + fabsf(hy * cosa);
    float* A = &g_aabb[r * 6];
    A[0] = cx - ex; A[1] = cx + ex;
    A[2] = cy - ey; A[3] = cy + ey;
    A[4] = czc - hz; A[5] = czc + hz;
}

// ---------------------------------------------------------------------------
// Kernel 2: zero out (float4), zero counts, build bin->roi masks.
// Edge bins extend to +/-inf so clamped out-of-domain points stay correct.
// ---------------------------------------------------------------------------
__global__ void roi_setup_kernel(float* __restrict__ out, long total_out, int N) {
    int tid = blockIdx.x * blockDim.x + threadIdx.x;
    int nth = gridDim.x * blockDim.x;

    long nv4 = total_out >> 2;
    float4 z4 = make_float4(0.f, 0.f, 0.f, 0.f);
    float4* o4 = (float4*)out;
    for (long i = tid; i < nv4; i += nth) o4[i] = z4;
    for (long i = (nv4 << 2) + tid; i < total_out; i += nth) out[i] = 0.0f;

    long nc = (long)N * V_G;
    for (long i = tid; i < nc; i += nth) g_count[i] = 0;

    int nw = (N + 63) >> 6;
    for (int b = tid; b < NBINS; b += nth) {
        int bx = b % NB, by = (b / NB) % NB, bz = b / (NB * NB);
        float x0 = (bx == 0)      ? -3e38f : DOM_LO + bx * CELL;
        float x1 = (bx == NB - 1) ?  3e38f : DOM_LO + (bx + 1) * CELL;
        float y0 = (by == 0)      ? -3e38f : DOM_LO + by * CELL;
        float y1 = (by == NB - 1) ?  3e38f : DOM_LO + (by + 1) * CELL;
        float z0 = (bz == 0)      ? -3e38f : DOM_LO + bz * CELL;
        float z1 = (bz == NB - 1) ?  3e38f : DOM_LO + (bz + 1) * CELL;
        for (int w = 0; w < nw; w++) {
            unsigned long long m = 0ull;
            int rend = min(N, (w + 1) << 6);
            for (int r = (w << 6); r < rend; r++) {
                const float* A = &g_aabb[r * 6];
                bool ov = (A[0] <= x1) & (A[1] >= x0) &
                          (A[2] <= y1) & (A[3] >= y0) &
                          (A[4] <= z1) & (A[5] >= z0);
                if (ov) m |= 1ull << (r & 63);
            }
            g_mask[(long)b * NWMAX + w] = m;
        }
    }
}

// ---------------------------------------------------------------------------
// Kernel 3: one thread per point. Bin lookup -> exact test only on mask bits.
// First hit of a voxel (atomicAdd returns 0) appends it to g_touched.
// ---------------------------------------------------------------------------
__global__ void roi_points_kernel(const float* __restrict__ pts,
                                  const float* __restrict__ feat,
                                  const int* __restrict__ mode_p,
                                  float* __restrict__ out,
                                  int N, int P, int C) {
    __shared__ float s_roi[MAXN * 12];
    int nfl = N * 12;
    for (int i = threadIdx.x; i < nfl; i += blockDim.x)
        s_roi[i] = g_roi[i];
    __syncthreads();

    int p = blockIdx.x * blockDim.x + threadIdx.x;
    if (p >= P) return;

    float px = __ldg(&pts[3 * p + 0]);
    float py = __ldg(&pts[3 * p + 1]);
    float pz = __ldg(&pts[3 * p + 2]);

    const float invcell = 1.0f / CELL;
    int bx = min(NB - 1, max(0, (int)((px - DOM_LO) * invcell)));
    int by = min(NB - 1, max(0, (int)((py - DOM_LO) * invcell)));
    int bz = min(NB - 1, max(0, (int)((pz - DOM_LO) * invcell)));
    int bin = (bz * NB + by) * NB + bx;

    int nw = (N + 63) >> 6;
    int mode = __ldg(mode_p);

    for (int w = 0; w < nw; w++) {
        unsigned long long m = __ldg(&g_mask[(long)bin * NWMAX + w]);
        while (m) {
            int bit = __ffsll((long long)m) - 1;
            m &= m - 1;
            int r = (w << 6) + bit;
            const float* R = &s_roi[r * 12];

            float lz = pz - R[2];
            float hz = R[7];
            if (fabsf(lz) > hz) continue;
            float sx = px - R[0];
            float sy = py - R[1];
            if (sx * sx + sy * sy > R[11]) continue;
            float cosa = R[3], sina = R[4];
            float lx = sx * cosa - sy * sina;
            float ly = sx * sina + sy * cosa;
            float hx = R[5], hy = R[6];
            if (fabsf(lx) >= hx) continue;
            if (fabsf(ly) >= hy) continue;

            int xi = min(max((int)floorf((lx + hx) / R[8]), 0), OUT_G - 1);
            int yi = min(max((int)floorf((ly + hy) / R[9]), 0), OUT_G - 1);
            int zi = min(max((int)floorf((lz + hz) / R[10]), 0), OUT_G - 1);
            int rv = r * V_G + (xi * OUT_G + yi) * OUT_G + zi;

            int old = atomicAdd(&g_count[rv], 1);
            if (old == 0) {
                int slot = atomicAdd(&g_ntouched, 1);
                g_touched[slot] = rv;
            }
            long base = (long)rv * C;

            if ((C & 3) == 0) {
                const float4* fp4 = (const float4*)(feat + (long)p * C);
                if (mode == 0) {
                    unsigned* o = reinterpret_cast<unsigned*>(out) + base;
                    for (int c4 = 0; c4 < (C >> 2); c4++) {
                        float4 f = __ldg(fp4 + c4);
                        atomicMax(o + 4 * c4 + 0, enc_f(f.x));
                        atomicMax(o + 4 * c4 + 1, enc_f(f.y));
                        atomicMax(o + 4 * c4 + 2, enc_f(f.z));
                        atomicMax(o + 4 * c4 + 3, enc_f(f.w));
                    }
                } else {
                    float* o = out + base;
                    for (int c4 = 0; c4 < (C >> 2); c4++) {
                        float4 f = __ldg(fp4 + c4);
                        atomicAdd(o + 4 * c4 + 0, f.x);
                        atomicAdd(o + 4 * c4 + 1, f.y);
                        atomicAdd(o + 4 * c4 + 2, f.z);
                        atomicAdd(o + 4 * c4 + 3, f.w);
                    }
                }
            } else {
                const float* fp = feat + (long)p * C;
                if (mode == 0) {
                    unsigned* o = reinterpret_cast<unsigned*>(out) + base;
                    for (int c = 0; c < C; c++) atomicMax(o + c, enc_f(__ldg(fp + c)));
                } else {
                    float* o = out + base;
                    for (int c = 0; c < C; c++) atomicAdd(o + c, __ldg(fp + c));
                }
            }
        }
    }
}

// ---------------------------------------------------------------------------
// Kernel 4: finalize over the touched list only. chunks = elements (C%4!=0)
// or float4 chunks (C%4==0). Last block out resets g_ntouched/g_done so every
// graph replay starts clean.
// ---------------------------------------------------------------------------
__global__ void roi_finalize_list_kernel(const int* __restrict__ mode_p,
                                         float* __restrict__ out,
                                         int C) {
    int n = g_ntouched;           // all blocks read before any block can reset
    int mode = __ldg(mode_p);
    int nth = gridDim.x * blockDim.x;
    int tid = blockIdx.x * blockDim.x + threadIdx.x;

    if ((C & 3) == 0) {
        int c4pv = C >> 2;
        int total = n * c4pv;
        for (int t = tid; t < total; t += nth) {
            int li = t / c4pv;
            int ch = t - li * c4pv;
            int v = g_touched[li];
            float4* o4 = reinterpret_cast<float4*>(out) + (long)v * c4pv + ch;
            float4 f = *o4;
            if (mode == 0) {
                f.x = dec_f(__float_as_uint(f.x));
                f.y = dec_f(__float_as_uint(f.y));
                f.z = dec_f(__float_as_uint(f.z));
                f.w = dec_f(__float_as_uint(f.w));
            } else {
                float inv = 1.0f / (float)__ldg(&g_count[v]);
                f.x *= inv; f.y *= inv; f.z *= inv; f.w *= inv;
            }
            *o4 = f;
        }
    } else {
        int total = n * C;
        for (int t = tid; t < total; t += nth) {
            int li = t / C;
            int ch = t - li * C;
            int v = g_touched[li];
            long idx = (long)v * C + ch;
            if (mode == 0) {
                unsigned u = reinterpret_cast<unsigned*>(out)[idx];
                out[idx] = dec_f(u);
            } else {
                out[idx] = out[idx] / (float)__ldg(&g_count[v]);
            }
        }
    }

    // last-block-out cleanup (self-cleaning scratch for the next graph replay)
    __syncthreads();
    if (threadIdx.x == 0) {
        __threadfence();
        int d = atomicAdd(&g_done, 1);
        if (d == (int)gridDim.x - 1) {
            g_ntouched = 0;
            g_done = 0;
        }
    }
}

extern "C" void kernel_launch(void* const* d_in, const int* in_sizes, int n_in,
                              void* d_out, int out_size) {
    const float* rois = (const float*)d_in[0];
    const float* pts = (const float*)d_in[1];
    const float* feat = (const float*)d_in[2];
    const int* mode_p = (const int*)d_in[3];
    float* out = (float*)d_out;

    int N = in_sizes[0] / 7;          // 64
    int P = in_sizes[1] / 3;          // 100000
    int C = in_sizes[2] / P;          // 16
    long total_out = (long)out_size;  // N*V*C

    roi_params_kernel<<<(N + 255) / 256, 256>>>(rois, N);
    roi_setup_kernel<<<1024, 256>>>(out, total_out, N);
    roi_points_kernel<<<(P + 255) / 256, 256>>>(pts, feat, mode_p, out, N, P, C);
    roi_finalize_list_kernel<<<FIN_BLOCKS, FIN_THREADS>>>(mode_p, out, C);
}

// round 11
// speedup vs baseline: 1.7306x; 1.7306x over previous
#include <cuda_runtime.h>
#include <cuda_bf16.h>
#include <math.h>

#define OUT_G 12
#define V_G (OUT_G * OUT_G * OUT_G)   // 1728
#define MAXN 256
#define MAXC 64
#define NB 16                          // spatial bins per dim
#define NBINS (NB * NB * NB)           // 4096
#define NWMAX 4                        // mask words (up to 256 rois)
#define DOM_LO (-12.0f)
#define DOM_HI (12.0f)
#define CELL ((DOM_HI - DOM_LO) / (float)NB)   // 1.5

// Scratch (__device__ globals: allocation-free rule).
// g_scratch invariant: all-zero at kernel_launch entry (BSS gives the base
// case; finalize resets every chunk it consumed). g_count is zeroed by setup
// each run. out itself is never pre-zeroed.
__device__ unsigned g_scratch[MAXN * V_G * MAXC];
__device__ int g_count[MAXN * V_G];
__device__ unsigned long long g_mask[NBINS * NWMAX];

__device__ __forceinline__ unsigned enc_f(float f) {
    unsigned u = __float_as_uint(f);
    return (u & 0x80000000u) ? ~u : (u | 0x80000000u);
}
__device__ __forceinline__ float dec_f(unsigned u) {
    return (u & 0x80000000u) ? __uint_as_float(u & 0x7FFFFFFFu) : __uint_as_float(~u);
}

// ---------------------------------------------------------------------------
// Kernel 1: zero counts + build bin->roi AABB masks (AABBs computed in smem).
// Edge bins extend to +/-inf so out-of-domain points stay correct.
// ---------------------------------------------------------------------------
__global__ void roi_setup_kernel(const float* __restrict__ rois, int N) {
    __shared__ float s_aabb[MAXN * 6];
    for (int r = threadIdx.x; r < N; r += blockDim.x) {
        float cx = rois[7 * r + 0];
        float cy = rois[7 * r + 1];
        float czb = rois[7 * r + 2];
        float dx = rois[7 * r + 3];
        float dy = rois[7 * r + 4];
        float dz = rois[7 * r + 5];
        float rz = rois[7 * r + 6];
        float czc = czb + dz * 0.5f;
        float cosa = cosf(-rz);
        float sina = sinf(-rz);
        float hx = dx * 0.5f, hy = dy * 0.5f, hz = dz * 0.5f;
        float ex = fabsf(hx * cosa) + fabsf(hy * sina);
        float ey = fabsf(hx * sina) + fabsf(hy * cosa);
        float* A = &s_aabb[r * 6];
        A[0] = cx - ex; A[1] = cx + ex;
        A[2] = cy - ey; A[3] = cy + ey;
        A[4] = czc - hz; A[5] = czc + hz;
    }
    __syncthreads();

    int tid = blockIdx.x * blockDim.x + threadIdx.x;
    int nth = gridDim.x * blockDim.x;

    long nc = (long)N * V_G;
    for (long i = tid; i < nc; i += nth) g_count[i] = 0;

    int nw = (N + 63) >> 6;
    for (int b = tid; b < NBINS; b += nth) {
        int bx = b % NB, by = (b / NB) % NB, bz = b / (NB * NB);
        float x0 = (bx == 0)      ? -3e38f : DOM_LO + bx * CELL;
        float x1 = (bx == NB - 1) ?  3e38f : DOM_LO + (bx + 1) * CELL;
        float y0 = (by == 0)      ? -3e38f : DOM_LO + by * CELL;
        float y1 = (by == NB - 1) ?  3e38f : DOM_LO + (by + 1) * CELL;
        float z0 = (bz == 0)      ? -3e38f : DOM_LO + bz * CELL;
        float z1 = (bz == NB - 1) ?  3e38f : DOM_LO + (bz + 1) * CELL;
        for (int w = 0; w < nw; w++) {
            unsigned long long m = 0ull;
            int rend = min(N, (w + 1) << 6);
            for (int r = (w << 6); r < rend; r++) {
                const float* A = &s_aabb[r * 6];
                bool ov = (A[0] <= x1) & (A[1] >= x0) &
                          (A[2] <= y1) & (A[3] >= y0) &
                          (A[4] <= z1) & (A[5] >= z0);
                if (ov) m |= 1ull << (r & 63);
            }
            g_mask[(long)b * NWMAX + w] = m;
        }
    }
}

// ---------------------------------------------------------------------------
// Kernel 2: one thread per point. Roi params computed into smem from rois
// directly. Bin lookup -> exact test only on mask bits. Atomics into scratch.
// ---------------------------------------------------------------------------
__global__ void roi_points_kernel(const float* __restrict__ rois,
                                  const float* __restrict__ pts,
                                  const float* __restrict__ feat,
                                  const int* __restrict__ mode_p,
                                  int N, int P, int C) {
    __shared__ float s_roi[MAXN * 12];
    for (int r = threadIdx.x; r < N; r += blockDim.x) {
        float cx = rois[7 * r + 0];
        float cy = rois[7 * r + 1];
        float czb = rois[7 * r + 2];
        float dx = rois[7 * r + 3];
        float dy = rois[7 * r + 4];
        float dz = rois[7 * r + 5];
        float rz = rois[7 * r + 6];
        float czc = czb + dz * 0.5f;
        float cosa = cosf(-rz);
        float sina = sinf(-rz);
        float hx = dx * 0.5f, hy = dy * 0.5f, hz = dz * 0.5f;
        float* R = &s_roi[r * 12];
        R[0] = cx; R[1] = cy; R[2] = czc; R[3] = cosa; R[4] = sina;
        R[5] = hx; R[6] = hy; R[7] = hz;
        R[8] = dx / (float)OUT_G; R[9] = dy / (float)OUT_G; R[10] = dz / (float)OUT_G;
        R[11] = hx * hx + hy * hy;
    }
    __syncthreads();

    int p = blockIdx.x * blockDim.x + threadIdx.x;
    if (p >= P) return;

    float px = __ldg(&pts[3 * p + 0]);
    float py = __ldg(&pts[3 * p + 1]);
    float pz = __ldg(&pts[3 * p + 2]);

    const float invcell = 1.0f / CELL;
    int bx = min(NB - 1, max(0, (int)((px - DOM_LO) * invcell)));
    int by = min(NB - 1, max(0, (int)((py - DOM_LO) * invcell)));
    int bz = min(NB - 1, max(0, (int)((pz - DOM_LO) * invcell)));
    int bin = (bz * NB + by) * NB + bx;

    int nw = (N + 63) >> 6;
    int mode = __ldg(mode_p);

    for (int w = 0; w < nw; w++) {
        unsigned long long m = __ldg(&g_mask[(long)bin * NWMAX + w]);
        while (m) {
            int bit = __ffsll((long long)m) - 1;
            m &= m - 1;
            int r = (w << 6) + bit;
            const float* R = &s_roi[r * 12];

            float lz = pz - R[2];
            float hz = R[7];
            if (fabsf(lz) > hz) continue;
            float sx = px - R[0];
            float sy = py - R[1];
            if (sx * sx + sy * sy > R[11]) continue;
            float cosa = R[3], sina = R[4];
            float lx = sx * cosa - sy * sina;
            float ly = sx * sina + sy * cosa;
            float hx = R[5], hy = R[6];
            if (fabsf(lx) >= hx) continue;
            if (fabsf(ly) >= hy) continue;

            int xi = min(max((int)floorf((lx + hx) / R[8]), 0), OUT_G - 1);
            int yi = min(max((int)floorf((ly + hy) / R[9]), 0), OUT_G - 1);
            int zi = min(max((int)floorf((lz + hz) / R[10]), 0), OUT_G - 1);
            int rv = r * V_G + (xi * OUT_G + yi) * OUT_G + zi;

            atomicAdd(&g_count[rv], 1);          // fire-and-forget -> REDG
            long base = (long)rv * C;

            if ((C & 3) == 0) {
                const float4* fp4 = (const float4*)(feat + (long)p * C);
                if (mode == 0) {
                    unsigned* o = g_scratch + base;
                    for (int c4 = 0; c4 < (C >> 2); c4++) {
                        float4 f = __ldg(fp4 + c4);
                        atomicMax(o + 4 * c4 + 0, enc_f(f.x));
                        atomicMax(o + 4 * c4 + 1, enc_f(f.y));
                        atomicMax(o + 4 * c4 + 2, enc_f(f.z));
                        atomicMax(o + 4 * c4 + 3, enc_f(f.w));
                    }
                } else {
                    float* o = reinterpret_cast<float*>(g_scratch) + base;
                    for (int c4 = 0; c4 < (C >> 2); c4++) {
                        float4 f = __ldg(fp4 + c4);
                        atomicAdd(o + 4 * c4 + 0, f.x);
                        atomicAdd(o + 4 * c4 + 1, f.y);
                        atomicAdd(o + 4 * c4 + 2, f.z);
                        atomicAdd(o + 4 * c4 + 3, f.w);
                    }
                }
            } else {
                const float* fp = feat + (long)p * C;
                if (mode == 0) {
                    unsigned* o = g_scratch + base;
                    for (int c = 0; c < C; c++) atomicMax(o + c, enc_f(__ldg(fp + c)));
                } else {
                    float* o = reinterpret_cast<float*>(g_scratch) + base;
                    for (int c = 0; c < C; c++) atomicAdd(o + c, __ldg(fp + c));
                }
            }
        }
    }
}

// ---------------------------------------------------------------------------
// Kernel 3a: finalize (C % 4 == 0). One thread per float4 chunk, coalesced.
// Streams the whole output; empty voxels write 0 without touching scratch.
// Occupied chunks: read scratch, decode/divide, reset scratch (own chunk --
// race-free), write out.
// ---------------------------------------------------------------------------
__global__ void roi_finalize_vec_kernel(const int* __restrict__ mode_p,
                                        float* __restrict__ out,
                                        int c4pv, int total4) {
    int i = blockIdx.x * blockDim.x + threadIdx.x;
    if (i >= total4) return;
    int v = i / c4pv;
    int cnt = __ldg(&g_count[v]);
    float4 f = make_float4(0.f, 0.f, 0.f, 0.f);
    if (cnt > 0) {
        uint4* s4 = reinterpret_cast<uint4*>(g_scratch) + i;
        uint4 s = *s4;
        if (__ldg(mode_p) == 0) {
            f.x = dec_f(s.x); f.y = dec_f(s.y);
            f.z = dec_f(s.z); f.w = dec_f(s.w);
        } else {
            float inv = 1.0f / (float)cnt;
            f.x = __uint_as_float(s.x) * inv;
            f.y = __uint_as_float(s.y) * inv;
            f.z = __uint_as_float(s.z) * inv;
            f.w = __uint_as_float(s.w) * inv;
        }
        *s4 = make_uint4(0u, 0u, 0u, 0u);   // restore invariant
    }
    reinterpret_cast<float4*>(out)[i] = f;
}

// ---------------------------------------------------------------------------
// Kernel 3b: generic finalize, one thread per element.
// ---------------------------------------------------------------------------
__global__ void roi_finalize_gen_kernel(const int* __restrict__ mode_p,
                                        float* __restrict__ out,
                                        int C, long total) {
    long i = (long)blockIdx.x * blockDim.x + threadIdx.x;
    if (i >= total) return;
    int v = (int)(i / C);
    int cnt = __ldg(&g_count[v]);
    float f = 0.0f;
    if (cnt > 0) {
        unsigned s = g_scratch[i];
        if (__ldg(mode_p) == 0) f = dec_f(s);
        else f = __uint_as_float(s) / (float)cnt;
        g_scratch[i] = 0u;
    }
    out[i] = f;
}

extern "C" void kernel_launch(void* const* d_in, const int* in_sizes, int n_in,
                              void* d_out, int out_size) {
    const float* rois = (const float*)d_in[0];
    const float* pts = (const float*)d_in[1];
    const float* feat = (const float*)d_in[2];
    const int* mode_p = (const int*)d_in[3];
    float* out = (float*)d_out;

    int N = in_sizes[0] / 7;          // 64
    int P = in_sizes[1] / 3;          // 100000
    int C = in_sizes[2] / P;          // 16
    long total_out = (long)out_size;  // N*V*C

    roi_setup_kernel<<<64, 256>>>(rois, N);
    roi_points_kernel<<<(P + 255) / 256, 256>>>(rois, pts, feat, mode_p, N, P, C);

    if ((C & 3) == 0) {
        int c4pv = C >> 2;
        int total4 = (int)(total_out >> 2);
        roi_finalize_vec_kernel<<<(total4 + 255) / 256, 256>>>(mode_p, out, c4pv, total4);
    } else {
        roi_finalize_gen_kernel<<<(int)((total_out + 255) / 256), 256>>>(mode_p, out, C, total_out);
    }
}